// round 3
// baseline (speedup 1.0000x reference)
#include <cuda_runtime.h>
#include <cuda_bf16.h>
#include <cstdint>

// Problem constants: B=16 graphs, N=4096 nodes/graph, 64 features, k=10.
#define KNN_K      10
#define BGRAPHS    16
#define FEATS      64
#define MAX_TOTAL  65536
#define QPB        256      // queries per block
#define TPB        512      // 2 threads per query

// Scratch (device globals: no allocation allowed in kernel_launch)
__device__ float g_sum[MAX_TOTAL * FEATS];   // 16 MB accumulators
__device__ int   g_cnt[MAX_TOTAL];           // reverse-degree counts
__device__ int   g_nbr[MAX_TOTAL * KNN_K];   // knn neighbor lists (global idx)

// ---------- packed f32x2 helpers (sm_103a) ----------
__device__ __forceinline__ uint64_t pack2(float a, float b) {
    uint64_t r; asm("mov.b64 %0, {%1, %2};" : "=l"(r) : "f"(a), "f"(b)); return r;
}
__device__ __forceinline__ void unpack2(float& lo, float& hi, uint64_t v) {
    asm("mov.b64 {%0, %1}, %2;" : "=f"(lo), "=f"(hi) : "l"(v));
}
__device__ __forceinline__ uint64_t mul2(uint64_t a, uint64_t b) {
    uint64_t r; asm("mul.rn.f32x2 %0, %1, %2;" : "=l"(r) : "l"(a), "l"(b)); return r;
}
__device__ __forceinline__ uint64_t add2(uint64_t a, uint64_t b) {
    uint64_t r; asm("add.rn.f32x2 %0, %1, %2;" : "=l"(r) : "l"(a), "l"(b)); return r;
}
__device__ __forceinline__ uint64_t fma2(uint64_t a, uint64_t b, uint64_t c) {
    uint64_t r; asm("fma.rn.f32x2 %0, %1, %2, %3;" : "=l"(r) : "l"(a), "l"(b), "l"(c)); return r;
}

// sorted-ascending ripple insert of one u64 key into kd[0..9]
#define INS(cin) do {                                                     \
    uint64_t c_ = (cin);                                                  \
    _Pragma("unroll")                                                     \
    for (int t_ = 0; t_ < KNN_K; ++t_) {                                  \
        uint64_t mn_ = (c_ < kd[t_]) ? c_ : kd[t_];                       \
        uint64_t mx_ = (c_ < kd[t_]) ? kd[t_] : c_;                       \
        kd[t_] = mn_; c_ = mx_;                                           \
    }                                                                     \
} while (0)

#define FLUSH() do {                                                      \
    if (n > 0) {                                                          \
        INS(bu0);                                                         \
        if (n > 1) INS(bu1);                                              \
        if (n > 2) INS(bu2);                                              \
        if (n > 3) INS(bu3);                                              \
        n = 0;                                                            \
    }                                                                     \
    thr = __uint_as_float((unsigned)(kd[KNN_K - 1] >> 32));               \
} while (0)

#define PUSH(dv, cv) do {                                                 \
    uint64_t key_ = ((uint64_t)__float_as_uint(dv) << 32) | (unsigned)(cv); \
    bu0 = (n == 0) ? key_ : bu0;                                          \
    bu1 = (n == 1) ? key_ : bu1;                                          \
    bu2 = (n == 2) ? key_ : bu2;                                          \
    bu3 = (n == 3) ? key_ : bu3;                                          \
    n++;                                                                  \
} while (0)

// ---------------------------------------------------------------------------
// K1: brute-force kNN, 2 threads/query, buffered top-10 with u64 keys.
// smem pair-transposed: sxy[jp]={x0,x1,y0,y1}, szw[jp]={z0,z1,w0,w1}, w=|p|^2
// d2 = (qsq + w) - 2*dot  (same rounding order as reference formula).
// key = (d2_bits << 32) | idx  -> u64 compare == (distance, then index) order,
// exactly matching jax.lax.top_k tie semantics. d2(self) == 0.0 exactly
// (identical op order for w and dot), excluded by index check at push.
// ---------------------------------------------------------------------------
__global__ void __launch_bounds__(TPB) knn_kernel(const float* __restrict__ pos, int N) {
    extern __shared__ float4 sm[];
    float4* sxy = sm;             // N/2 entries
    float4* szw = sm + (N >> 1);  // N/2 entries

    const int tilesPerGraph = N / QPB;
    const int b    = blockIdx.x / tilesPerGraph;
    const int tile = blockIdx.x % tilesPerGraph;
    const int tid  = threadIdx.x;

    // ---- fused zeroing: this block owns queries [qbase, qbase+QPB) ----
    const int qbase = b * N + tile * QPB;
    {
        float4 z = make_float4(0.f, 0.f, 0.f, 0.f);
        float4* dst = reinterpret_cast<float4*>(g_sum) + (size_t)qbase * (FEATS / 4);
#pragma unroll
        for (int i = 0; i < (QPB * FEATS / 4) / TPB; ++i) dst[i * TPB + tid] = z;
        if (tid < QPB) g_cnt[qbase + tid] = 0;
    }

    // ---- stage positions (pair-transposed) ----
    const float* pg = pos + (size_t)b * N * 3;
    for (int jp = tid; jp < (N >> 1); jp += TPB) {
        int j0 = jp * 2;
        float x0 = pg[3*j0+0], y0 = pg[3*j0+1], z0 = pg[3*j0+2];
        float x1 = pg[3*j0+3], y1 = pg[3*j0+4], z1 = pg[3*j0+5];
        float w0 = x0*x0 + y0*y0 + z0*z0;
        float w1 = x1*x1 + y1*y1 + z1*z1;
        sxy[jp] = make_float4(x0, x1, y0, y1);
        szw[jp] = make_float4(z0, z1, w0, w1);
    }
    __syncthreads();

    // ---- own query: q = tid>>1, half = tid&1 ----
    const int q  = tid >> 1;
    const int h  = tid & 1;
    const int ql = tile * QPB + q;        // local query index in graph
    float qx, qy, qz, qsq;
    {
        float4 xy = sxy[ql >> 1];
        float4 zw = szw[ql >> 1];
        if (ql & 1) { qx = xy.y; qy = xy.w; qz = zw.y; qsq = zw.w; }
        else        { qx = xy.x; qy = xy.z; qz = zw.x; qsq = zw.z; }
    }
    const uint64_t qx2  = pack2(qx, qx);
    const uint64_t qy2  = pack2(qy, qy);
    const uint64_t qz2  = pack2(qz, qz);
    const uint64_t qsq2 = pack2(qsq, qsq);
    const uint64_t m2   = pack2(-2.0f, -2.0f);

    uint64_t kd[KNN_K];
#pragma unroll
    for (int t = 0; t < KNN_K; ++t) kd[t] = 0x7f800000ffffffffULL;
    float thr = __int_as_float(0x7f800000);
    uint64_t bu0 = 0, bu1 = 0, bu2 = 0, bu3 = 0;
    int n = 0;

    const ulonglong2* pxy = reinterpret_cast<const ulonglong2*>(sxy);
    const ulonglong2* pzw = reinterpret_cast<const ulonglong2*>(szw);

    const int jpBeg = h * (N >> 2);       // each half scans N/4 pairs
    const int jpEnd = jpBeg + (N >> 2);

    for (int jp = jpBeg; jp < jpEnd; ++jp) {
        // warp-uniform flush check (caps buffer growth at 4)
        if (__any_sync(0xffffffffu, n >= 3)) { FLUSH(); }

        ulonglong2 xy = pxy[jp];   // {x0,x1},{y0,y1}
        ulonglong2 zw = pzw[jp];   // {z0,z1},{w0,w1}
        uint64_t dot = mul2(qx2, xy.x);
        dot = fma2(qy2, xy.y, dot);
        dot = fma2(qz2, zw.x, dot);
        uint64_t s2  = add2(qsq2, zw.y);
        uint64_t d2p = fma2(m2, dot, s2);
        float lo, hi; unpack2(lo, hi, d2p);

        if (fminf(lo, hi) < thr) {
            int j0 = jp * 2;
            if (lo < thr && j0 != ql)       PUSH(lo, j0);
            if (hi < thr && (j0 + 1) != ql) PUSH(hi, j0 + 1);
        }
    }
    FLUSH();

    // ---- merge the two halves: bitonic min of sorted lists ----
    uint64_t other[KNN_K];
#pragma unroll
    for (int t = 0; t < KNN_K; ++t)
        other[t] = __shfl_xor_sync(0xffffffffu, kd[t], 1);
#pragma unroll
    for (int t = 0; t < KNN_K; ++t) {
        uint64_t r = other[KNN_K - 1 - t];
        kd[t] = (kd[t] < r) ? kd[t] : r;   // set of 10 smallest of the union
    }

    if (h == 0) {
        const int qg = qbase + q;
#pragma unroll
        for (int t = 0; t < KNN_K; ++t)
            g_nbr[qg * KNN_K + t] = b * N + (int)(unsigned)kd[t];
    }
}

// ---------------------------------------------------------------------------
// K2: scatter x[query] into g_sum[neighbor] with vectorized L2 reductions,
// plus reverse-degree counting (lane 0 of each 16-lane query group).
// ---------------------------------------------------------------------------
__global__ void scatter_kernel(const float* __restrict__ x, int total) {
    int t = blockIdx.x * blockDim.x + threadIdx.x;
    int q = t >> 4;
    int c = t & 15;
    if (q >= total) return;

    float4 v = reinterpret_cast<const float4*>(x)[q * (FEATS / 4) + c];
    const int* nb = &g_nbr[q * KNN_K];

#pragma unroll
    for (int n = 0; n < KNN_K; ++n) {
        int j = nb[n];
        float* p = g_sum + (size_t)j * FEATS + c * 4;
        asm volatile("red.global.add.v4.f32 [%0], {%1, %2, %3, %4};"
                     :: "l"(p), "f"(v.x), "f"(v.y), "f"(v.z), "f"(v.w)
                     : "memory");
        if (c == 0)
            asm volatile("red.global.add.u32 [%0], %1;"
                         :: "l"(&g_cnt[j]), "r"(1) : "memory");
    }
}

// ---------------------------------------------------------------------------
// K3: out[r] = sum_d | x[r,d] - sum[r,d] / max(cnt[r],1) |   (warp per node)
// ---------------------------------------------------------------------------
__global__ void out_kernel(const float* __restrict__ x, float* __restrict__ out,
                           int total) {
    int node = (blockIdx.x * blockDim.x + threadIdx.x) >> 5;
    int lane = threadIdx.x & 31;
    if (node >= total) return;

    float c   = (float)g_cnt[node];
    float inv = 1.0f / fmaxf(c, 1.0f);

    const float* xr = x + (size_t)node * FEATS;
    const float* sr = g_sum + (size_t)node * FEATS;

    float acc = fabsf(xr[lane]      - sr[lane]      * inv)
              + fabsf(xr[lane + 32] - sr[lane + 32] * inv);
#pragma unroll
    for (int o = 16; o > 0; o >>= 1) acc += __shfl_xor_sync(0xffffffffu, acc, o);
    if (lane == 0) out[node] = acc;
}

// ---------------------------------------------------------------------------
extern "C" void kernel_launch(void* const* d_in, const int* in_sizes, int n_in,
                              void* d_out, int out_size) {
    const float* x   = (const float*)d_in[0];   // [total, 64] fp32
    const float* pos = (const float*)d_in[1];   // [total, 3]  fp32

    const int total = in_sizes[0] / FEATS;      // 65536
    const int N     = total / BGRAPHS;          // 4096
    float* out = (float*)d_out;

    // K1: kNN with fused zeroing (dynamic smem = N * 16 bytes = 64 KB)
    size_t smem = (size_t)N * sizeof(float4);
    cudaFuncSetAttribute(knn_kernel, cudaFuncAttributeMaxDynamicSharedMemorySize,
                         (int)smem);
    knn_kernel<<<total / QPB, TPB, smem>>>(pos, N);

    // K2: vectorized atomic scatter + counts (16 lanes per query)
    int threads2 = total * 16;
    scatter_kernel<<<(threads2 + 127) / 128, 128>>>(x, total);

    // K3: finalize L1 norm (warp per node)
    out_kernel<<<(total * 32 + 255) / 256, 256>>>(x, out, total);
}

// round 4
// speedup vs baseline: 1.4884x; 1.4884x over previous
#include <cuda_runtime.h>
#include <cuda_bf16.h>
#include <cstdint>

// Problem constants: B=16 graphs, N=4096 nodes/graph, 64 features, k=10.
#define KNN_K      10
#define BGRAPHS    16
#define FEATS      64
#define MAX_TOTAL  65536
#define NODES      4096
#define QPB        256
#define NBUCKET    256

// Scratch (device globals: no allocation allowed in kernel_launch)
__device__ float  g_sum[MAX_TOTAL * FEATS];    // 16 MB accumulators
__device__ int    g_cnt[MAX_TOTAL];            // reverse-degree counts
__device__ int    g_nbr[MAX_TOTAL * KNN_K];    // knn neighbor lists (global idx)
__device__ float4 g_spos[MAX_TOTAL];           // sorted positions {x,y,z,|p|^2}
__device__ int    g_sidx[MAX_TOTAL];           // sorted-rank -> original local idx

// ---------- packed f32x2 helpers (sm_103a) ----------
__device__ __forceinline__ uint64_t pack2(float a, float b) {
    uint64_t r; asm("mov.b64 %0, {%1, %2};" : "=l"(r) : "f"(a), "f"(b)); return r;
}
__device__ __forceinline__ void unpack2(float& lo, float& hi, uint64_t v) {
    asm("mov.b64 {%0, %1}, %2;" : "=f"(lo), "=f"(hi) : "l"(v));
}
__device__ __forceinline__ uint64_t mul2(uint64_t a, uint64_t b) {
    uint64_t r; asm("mul.rn.f32x2 %0, %1, %2;" : "=l"(r) : "l"(a), "l"(b)); return r;
}
__device__ __forceinline__ uint64_t add2(uint64_t a, uint64_t b) {
    uint64_t r; asm("add.rn.f32x2 %0, %1, %2;" : "=l"(r) : "l"(a), "l"(b)); return r;
}
__device__ __forceinline__ uint64_t fma2(uint64_t a, uint64_t b, uint64_t c) {
    uint64_t r; asm("fma.rn.f32x2 %0, %1, %2, %3;" : "=l"(r) : "l"(a), "l"(b), "l"(c)); return r;
}

// sorted-ascending ripple insert of one u64 key (d2_bits<<32 | orig_idx)
#define INS(cin) do {                                                     \
    uint64_t c_ = (cin);                                                  \
    _Pragma("unroll")                                                     \
    for (int t_ = 0; t_ < KNN_K; ++t_) {                                  \
        uint64_t mn_ = (c_ < kd[t_]) ? c_ : kd[t_];                       \
        uint64_t mx_ = (c_ < kd[t_]) ? kd[t_] : c_;                       \
        kd[t_] = mn_; c_ = mx_;                                           \
    }                                                                     \
    thr = __uint_as_float((unsigned)(kd[KNN_K - 1] >> 32));               \
} while (0)

// ---------------------------------------------------------------------------
// K0: counting-sort each graph's points by x-bucket (clustering permutation;
// within-bucket order is arbitrary — results are exact regardless, since the
// top-10 is selected by a total order on (d2, orig_idx)).
// Also precomputes w = |p|^2.
// ---------------------------------------------------------------------------
__global__ void sort_kernel(const float* __restrict__ pos) {
    __shared__ int cnt[NBUCKET];
    __shared__ int inc[NBUCKET];
    __shared__ int off[NBUCKET];

    const int b   = blockIdx.x;
    const int tid = threadIdx.x;        // 256 threads
    const float* pg = pos + (size_t)b * NODES * 3;

    cnt[tid] = 0;
    __syncthreads();

    // histogram
    for (int j = tid; j < NODES; j += 256) {
        float x = pg[3 * j];
        int bk = (int)floorf((x + 4.0f) * 32.0f);
        bk = max(0, min(NBUCKET - 1, bk));
        atomicAdd(&cnt[bk], 1);
    }
    __syncthreads();

    // inclusive prefix sum (Hillis-Steele over 256 bins)
    inc[tid] = cnt[tid];
    __syncthreads();
    for (int d = 1; d < NBUCKET; d <<= 1) {
        int v = (tid >= d) ? inc[tid - d] : 0;
        __syncthreads();
        inc[tid] += v;
        __syncthreads();
    }
    off[tid] = inc[tid] - cnt[tid];     // exclusive start
    __syncthreads();

    // scatter
    for (int j = tid; j < NODES; j += 256) {
        float x = pg[3 * j], y = pg[3 * j + 1], z = pg[3 * j + 2];
        float w = x * x + y * y + z * z;
        int bk = (int)floorf((x + 4.0f) * 32.0f);
        bk = max(0, min(NBUCKET - 1, bk));
        int p = atomicAdd(&off[bk], 1);
        g_spos[b * NODES + p] = make_float4(x, y, z, w);
        g_sidx[b * NODES + p] = j;
    }
}

// ---------------------------------------------------------------------------
// K1: brute-force kNN over the x-sorted point set. Queries are assigned by
// sorted rank, so a warp's 32 queries are spatial neighbors; the circular
// scan starts 512 ranks below the warp center so per-lane thresholds reach
// near-final values within the first ~500 candidates, collapsing the
// divergent-insert frequency for the remaining ~3500.
// d2 = (qsq + w) - 2*dot with the reference's rounding order (f32x2 packed,
// per-lane IEEE identical). Self-distance is exactly 0; excluded by rank.
// ---------------------------------------------------------------------------
__global__ void __launch_bounds__(QPB) knn_kernel(int dummy) {
    extern __shared__ float4 sm[];
    float4* sxy  = sm;                        // N/2 pair-transposed {x0,x1,y0,y1}
    float4* szw  = sm + (NODES >> 1);         // N/2 pair-transposed {z0,z1,w0,w1}
    int*    ssid = (int*)(sm + NODES);        // N orig-idx per rank

    const int tilesPerGraph = NODES / QPB;    // 16
    const int b    = blockIdx.x / tilesPerGraph;
    const int tile = blockIdx.x % tilesPerGraph;
    const int tid  = threadIdx.x;
    const int gbase = b * NODES;

    // ---- fused zeroing of accumulators (rank-independent flat region) ----
    {
        float4 z = make_float4(0.f, 0.f, 0.f, 0.f);
        int nb = blockIdx.x * QPB;
        float4* dst = reinterpret_cast<float4*>(g_sum) + (size_t)nb * (FEATS / 4);
#pragma unroll
        for (int i = 0; i < 16; ++i) dst[i * QPB + tid] = z;
        g_cnt[nb + tid] = 0;
    }

    // ---- stage sorted positions (pair-transposed) + sorted->orig idx ----
    for (int jp = tid; jp < (NODES >> 1); jp += QPB) {
        float4 a = g_spos[gbase + 2 * jp];
        float4 c = g_spos[gbase + 2 * jp + 1];
        sxy[jp] = make_float4(a.x, c.x, a.y, c.y);
        szw[jp] = make_float4(a.z, c.z, a.w, c.w);
    }
    for (int j = tid; j < NODES; j += QPB)
        ssid[j] = g_sidx[gbase + j];
    __syncthreads();

    // ---- own query = sorted rank qr ----
    const int qr = tile * QPB + tid;
    float qx, qy, qz, qsq;
    {
        float4 xy = sxy[qr >> 1];
        float4 zw = szw[qr >> 1];
        if (qr & 1) { qx = xy.y; qy = xy.w; qz = zw.y; qsq = zw.w; }
        else        { qx = xy.x; qy = xy.z; qz = zw.x; qsq = zw.z; }
    }
    const uint64_t qx2  = pack2(qx, qx);
    const uint64_t qy2  = pack2(qy, qy);
    const uint64_t qz2  = pack2(qz, qz);
    const uint64_t qsq2 = pack2(qsq, qsq);
    const uint64_t m2   = pack2(-2.0f, -2.0f);

    uint64_t kd[KNN_K];
#pragma unroll
    for (int t = 0; t < KNN_K; ++t) kd[t] = 0x7f800000ffffffffULL;
    float thr = __int_as_float(0x7f800000);

    const ulonglong2* pxy = reinterpret_cast<const ulonglong2*>(sxy);
    const ulonglong2* pzw = reinterpret_cast<const ulonglong2*>(szw);

    // warp-uniform circular start: 512 ranks below the warp's query center
    const int wcenter = tile * QPB + ((tid >> 5) << 5) + 16;
    const int jpStart = ((wcenter - 512) & (NODES - 1)) >> 1;

#pragma unroll 4
    for (int t = 0; t < (NODES >> 1); ++t) {
        int jp = (jpStart + t) & ((NODES >> 1) - 1);
        ulonglong2 xy = pxy[jp];   // {x0,x1},{y0,y1}   (broadcast LDS)
        ulonglong2 zw = pzw[jp];   // {z0,z1},{w0,w1}
        uint64_t dot = mul2(qx2, xy.x);
        dot = fma2(qy2, xy.y, dot);
        dot = fma2(qz2, zw.x, dot);
        uint64_t s2  = add2(qsq2, zw.y);
        uint64_t d2p = fma2(m2, dot, s2);
        float lo, hi; unpack2(lo, hi, d2p);

        if (fminf(lo, hi) < thr) {
            int j0 = jp * 2;
            if (lo < thr && j0 != qr) {
                uint64_t key = ((uint64_t)__float_as_uint(lo) << 32)
                             | (unsigned)ssid[j0];
                INS(key);
            }
            if (hi < thr && (j0 + 1) != qr) {
                uint64_t key = ((uint64_t)__float_as_uint(hi) << 32)
                             | (unsigned)ssid[j0 + 1];
                INS(key);
            }
        }
    }

    // ---- write neighbor list for this query's ORIGINAL node id ----
    const int my_oid = gbase + ssid[qr];
#pragma unroll
    for (int t = 0; t < KNN_K; ++t)
        g_nbr[my_oid * KNN_K + t] = gbase + (int)(unsigned)kd[t];
}

// ---------------------------------------------------------------------------
// K2: scatter x[query] into g_sum[neighbor] with vectorized L2 reductions,
// plus reverse-degree counting (lane c==0 of each 16-lane query group).
// ---------------------------------------------------------------------------
__global__ void scatter_kernel(const float* __restrict__ x, int total) {
    int t = blockIdx.x * blockDim.x + threadIdx.x;
    int q = t >> 4;
    int c = t & 15;
    if (q >= total) return;

    float4 v = reinterpret_cast<const float4*>(x)[q * (FEATS / 4) + c];
    const int* nb = &g_nbr[q * KNN_K];

#pragma unroll
    for (int n = 0; n < KNN_K; ++n) {
        int j = nb[n];
        float* p = g_sum + (size_t)j * FEATS + c * 4;
        asm volatile("red.global.add.v4.f32 [%0], {%1, %2, %3, %4};"
                     :: "l"(p), "f"(v.x), "f"(v.y), "f"(v.z), "f"(v.w)
                     : "memory");
        if (c == 0)
            asm volatile("red.global.add.u32 [%0], %1;"
                         :: "l"(&g_cnt[j]), "r"(1) : "memory");
    }
}

// ---------------------------------------------------------------------------
// K3: out[r] = sum_d | x[r,d] - sum[r,d] / max(cnt[r],1) |   (warp per node)
// ---------------------------------------------------------------------------
__global__ void out_kernel(const float* __restrict__ x, float* __restrict__ out,
                           int total) {
    int node = (blockIdx.x * blockDim.x + threadIdx.x) >> 5;
    int lane = threadIdx.x & 31;
    if (node >= total) return;

    float c   = (float)g_cnt[node];
    float inv = 1.0f / fmaxf(c, 1.0f);

    const float* xr = x + (size_t)node * FEATS;
    const float* sr = g_sum + (size_t)node * FEATS;

    float acc = fabsf(xr[lane]      - sr[lane]      * inv)
              + fabsf(xr[lane + 32] - sr[lane + 32] * inv);
#pragma unroll
    for (int o = 16; o > 0; o >>= 1) acc += __shfl_xor_sync(0xffffffffu, acc, o);
    if (lane == 0) out[node] = acc;
}

// ---------------------------------------------------------------------------
extern "C" void kernel_launch(void* const* d_in, const int* in_sizes, int n_in,
                              void* d_out, int out_size) {
    const float* x   = (const float*)d_in[0];   // [total, 64] fp32
    const float* pos = (const float*)d_in[1];   // [total, 3]  fp32

    const int total = in_sizes[0] / FEATS;      // 65536
    float* out = (float*)d_out;

    // K0: per-graph counting sort by x (clustering permutation + w precompute)
    sort_kernel<<<BGRAPHS, 256>>>(pos);

    // K1: kNN over sorted order (smem: 64KB positions + 16KB idx = 80KB)
    size_t smem = (size_t)NODES * sizeof(float4) + NODES * sizeof(int);
    cudaFuncSetAttribute(knn_kernel, cudaFuncAttributeMaxDynamicSharedMemorySize,
                         (int)smem);
    knn_kernel<<<total / QPB, QPB, smem>>>(0);

    // K2: vectorized atomic scatter + counts (16 lanes per query)
    int threads2 = total * 16;
    scatter_kernel<<<(threads2 + 127) / 128, 128>>>(x, total);

    // K3: finalize L1 norm (warp per node)
    out_kernel<<<(total * 32 + 255) / 256, 256>>>(x, out, total);
}

// round 5
// speedup vs baseline: 1.6116x; 1.0828x over previous
#include <cuda_runtime.h>
#include <cuda_bf16.h>
#include <cstdint>

// Problem constants: B=16 graphs, N=4096 nodes/graph, 64 features, k=10.
#define KNN_K      10
#define BGRAPHS    16
#define FEATS      64
#define MAX_TOTAL  65536
#define NODES      4096
#define NPAIR      (NODES / 2)
#define QPB        256          // queries per block
#define TPB        512          // 2 threads per query
#define NBUCKET    256

// Scratch (device globals: no allocation allowed in kernel_launch)
__device__ float  g_sum[MAX_TOTAL * FEATS];    // 16 MB accumulators
__device__ int    g_cnt[MAX_TOTAL];            // reverse-degree counts
__device__ int    g_nbr[MAX_TOTAL * KNN_K];    // knn neighbor lists (global idx)
__device__ float4 g_spos[MAX_TOTAL];           // sorted positions {x,y,z,|p|^2}
__device__ int    g_sidx[MAX_TOTAL];           // sorted-rank -> original local idx

// ---------- packed f32x2 helpers (sm_103a) ----------
__device__ __forceinline__ uint64_t pack2(float a, float b) {
    uint64_t r; asm("mov.b64 %0, {%1, %2};" : "=l"(r) : "f"(a), "f"(b)); return r;
}
__device__ __forceinline__ void unpack2(float& lo, float& hi, uint64_t v) {
    asm("mov.b64 {%0, %1}, %2;" : "=f"(lo), "=f"(hi) : "l"(v));
}
__device__ __forceinline__ uint64_t mul2(uint64_t a, uint64_t b) {
    uint64_t r; asm("mul.rn.f32x2 %0, %1, %2;" : "=l"(r) : "l"(a), "l"(b)); return r;
}
__device__ __forceinline__ uint64_t add2(uint64_t a, uint64_t b) {
    uint64_t r; asm("add.rn.f32x2 %0, %1, %2;" : "=l"(r) : "l"(a), "l"(b)); return r;
}
__device__ __forceinline__ uint64_t fma2(uint64_t a, uint64_t b, uint64_t c) {
    uint64_t r; asm("fma.rn.f32x2 %0, %1, %2, %3;" : "=l"(r) : "l"(a), "l"(b), "l"(c)); return r;
}

// sorted-ascending ripple insert of one u64 key (d2_bits<<32 | orig_idx)
#define INS(cin) do {                                                     \
    uint64_t c_ = (cin);                                                  \
    _Pragma("unroll")                                                     \
    for (int t_ = 0; t_ < KNN_K; ++t_) {                                  \
        uint64_t mn_ = (c_ < kd[t_]) ? c_ : kd[t_];                       \
        uint64_t mx_ = (c_ < kd[t_]) ? kd[t_] : c_;                       \
        kd[t_] = mn_; c_ = mx_;                                           \
    }                                                                     \
    thr = __uint_as_float((unsigned)(kd[KNN_K - 1] >> 32));               \
} while (0)

// distance + conditional insert for one pair of candidates (fast path body)
#define PAIR_BODY(jp) do {                                                \
    ulonglong2 xy = pxy[jp];                                              \
    ulonglong2 zw = pzw[jp];                                              \
    uint64_t dot = mul2(qx2, xy.x);                                       \
    dot = fma2(qy2, xy.y, dot);                                           \
    dot = fma2(qz2, zw.x, dot);                                           \
    uint64_t s2  = add2(qsq2, zw.y);                                      \
    uint64_t d2p = fma2(m2, dot, s2);                                     \
    float lo, hi; unpack2(lo, hi, d2p);                                   \
    if (fminf(lo, hi) < thr) {                                            \
        int j0_ = (jp) * 2;                                               \
        if (lo < thr && j0_ != qr) {                                      \
            uint64_t key = ((uint64_t)__float_as_uint(lo) << 32)          \
                         | (unsigned)ssid[j0_];                           \
            INS(key);                                                     \
        }                                                                 \
        if (hi < thr && (j0_ + 1) != qr) {                                \
            uint64_t key = ((uint64_t)__float_as_uint(hi) << 32)          \
                         | (unsigned)ssid[j0_ + 1];                       \
            INS(key);                                                     \
        }                                                                 \
    }                                                                     \
} while (0)

// ---------------------------------------------------------------------------
// K0: counting-sort each graph's points by x-bucket. Within-bucket order is
// arbitrary (atomic order) — results stay exact because the top-10 is selected
// by a total order on (d2, orig_idx). Also precomputes w = |p|^2 with the
// reference's rounding order (mul, fma, fma).
// ---------------------------------------------------------------------------
__global__ void sort_kernel(const float* __restrict__ pos) {
    __shared__ int cnt[NBUCKET];
    __shared__ int inc[NBUCKET];
    __shared__ int off[NBUCKET];

    const int b   = blockIdx.x;
    const int tid = threadIdx.x;        // 512 threads
    const float* pg = pos + (size_t)b * NODES * 3;

    if (tid < NBUCKET) cnt[tid] = 0;
    __syncthreads();

    for (int j = tid; j < NODES; j += TPB) {
        float x = pg[3 * j];
        int bk = (int)floorf((x + 4.0f) * 32.0f);
        bk = max(0, min(NBUCKET - 1, bk));
        atomicAdd(&cnt[bk], 1);
    }
    __syncthreads();

    if (tid < NBUCKET) inc[tid] = cnt[tid];
    __syncthreads();
    for (int d = 1; d < NBUCKET; d <<= 1) {
        int v = 0;
        if (tid >= d && tid < NBUCKET) v = inc[tid - d];
        __syncthreads();
        if (tid < NBUCKET) inc[tid] += v;
        __syncthreads();
    }
    if (tid < NBUCKET) off[tid] = inc[tid] - cnt[tid];
    __syncthreads();

    for (int j = tid; j < NODES; j += TPB) {
        float x = pg[3 * j], y = pg[3 * j + 1], z = pg[3 * j + 2];
        float w = x * x + y * y + z * z;
        int bk = (int)floorf((x + 4.0f) * 32.0f);
        bk = max(0, min(NBUCKET - 1, bk));
        int p = atomicAdd(&off[bk], 1);
        g_spos[b * NODES + p] = make_float4(x, y, z, w);
        g_sidx[b * NODES + p] = j;
    }
}

// ---------------------------------------------------------------------------
// K1: kNN over the x-sorted point set. 2 threads per query:
//   warp w handles queries (w>>1)*32 .. +31, half h = w&1.
//   half h scans pairs of parity h in circular rank order starting 512 ranks
//   below the warp's query center — both halves retain spatial locality, so
//   thresholds converge within a few hundred candidates and the divergent
//   insert path nearly vanishes afterwards.
// Linear two-loop form (no per-iteration modulo), warp-uniform bounds,
// broadcast LDS. Halves merged exactly via smem + bitonic min on u64 keys.
// ---------------------------------------------------------------------------
__global__ void __launch_bounds__(TPB) knn_kernel(int dummy) {
    extern __shared__ float4 sm[];
    float4*   sxy  = sm;                      // NPAIR {x0,x1,y0,y1}
    float4*   szw  = sm + NPAIR;              // NPAIR {z0,z1,w0,w1}
    int*      ssid = (int*)(sm + NODES);      // NODES orig-idx per rank
    uint64_t* mbuf = (uint64_t*)sm;           // merge buffer (overlays sxy after scan)

    const int tilesPerGraph = NODES / QPB;    // 16
    const int b    = blockIdx.x / tilesPerGraph;
    const int tile = blockIdx.x % tilesPerGraph;
    const int tid  = threadIdx.x;
    const int gbase = b * NODES;

    // ---- fused zeroing of accumulators (block-flat region) ----
    {
        float4 z = make_float4(0.f, 0.f, 0.f, 0.f);
        int nb = blockIdx.x * QPB;
        float4* dst = reinterpret_cast<float4*>(g_sum) + (size_t)nb * (FEATS / 4);
#pragma unroll
        for (int i = 0; i < (QPB * FEATS / 4) / TPB; ++i) dst[i * TPB + tid] = z;
        if (tid < QPB) g_cnt[nb + tid] = 0;
    }

    // ---- stage sorted positions (pair-transposed) + rank->orig idx ----
    for (int jp = tid; jp < NPAIR; jp += TPB) {
        float4 a = g_spos[gbase + 2 * jp];
        float4 c = g_spos[gbase + 2 * jp + 1];
        sxy[jp] = make_float4(a.x, c.x, a.y, c.y);
        szw[jp] = make_float4(a.z, c.z, a.w, c.w);
    }
    for (int j = tid; j < NODES; j += TPB)
        ssid[j] = g_sidx[gbase + j];
    __syncthreads();

    // ---- thread -> (query, half) ----
    const int w  = tid >> 5;          // warp 0..15
    const int l  = tid & 31;
    const int h  = w & 1;             // scan-parity half
    const int q  = (w >> 1) * 32 + l; // query slot 0..255 in tile
    const int qr = tile * QPB + q;    // sorted rank of my query

    float qx, qy, qz, qsq;
    {
        float4 xy = sxy[qr >> 1];
        float4 zw = szw[qr >> 1];
        if (qr & 1) { qx = xy.y; qy = xy.w; qz = zw.y; qsq = zw.w; }
        else        { qx = xy.x; qy = xy.z; qz = zw.x; qsq = zw.z; }
    }
    const uint64_t qx2  = pack2(qx, qx);
    const uint64_t qy2  = pack2(qy, qy);
    const uint64_t qz2  = pack2(qz, qz);
    const uint64_t qsq2 = pack2(qsq, qsq);
    const uint64_t m2   = pack2(-2.0f, -2.0f);

    uint64_t kd[KNN_K];
#pragma unroll
    for (int t = 0; t < KNN_K; ++t) kd[t] = 0x7f800000ffffffffULL;
    float thr = __int_as_float(0x7f800000);

    const ulonglong2* pxy = reinterpret_cast<const ulonglong2*>(sxy);
    const ulonglong2* pzw = reinterpret_cast<const ulonglong2*>(szw);

    // warp-uniform circular start: 512 ranks below this warp's query center
    const int wcenter = tile * QPB + (w >> 1) * 32 + 16;
    const int sp = ((wcenter - 512) & (NODES - 1)) >> 1;   // start pair
    const int j0 = sp + h;                                  // my parity start

    // pairs j0, j0+2, ... wrapping at NPAIR; two linear loops, uniform bounds
#pragma unroll 4
    for (int jp = j0; jp < NPAIR; jp += 2) PAIR_BODY(jp);
#pragma unroll 4
    for (int jp = (j0 & 1); jp < j0; jp += 2) PAIR_BODY(jp);

    // ---- exact merge of the two halves (disjoint candidate sets) ----
    const int my_oid = gbase + ssid[qr];      // read before mbuf overlays? ssid separate ✓
    __syncthreads();                           // scans done; sxy reusable
    if (h == 1) {
#pragma unroll
        for (int t = 0; t < KNN_K; ++t) mbuf[q * KNN_K + t] = kd[t];
    }
    __syncthreads();
    if (h == 0) {
#pragma unroll
        for (int t = 0; t < KNN_K; ++t) {
            uint64_t r = mbuf[q * KNN_K + (KNN_K - 1 - t)];
            kd[t] = (kd[t] < r) ? kd[t] : r;  // 10 smallest of union (set)
        }
#pragma unroll
        for (int t = 0; t < KNN_K; ++t)
            g_nbr[my_oid * KNN_K + t] = gbase + (int)(unsigned)kd[t];
    }
}

// ---------------------------------------------------------------------------
// K2: scatter x[query] into g_sum[neighbor] with vectorized L2 reductions,
// plus reverse-degree counting (lane c==0 of each 16-lane query group).
// ---------------------------------------------------------------------------
__global__ void scatter_kernel(const float* __restrict__ x, int total) {
    int t = blockIdx.x * blockDim.x + threadIdx.x;
    int q = t >> 4;
    int c = t & 15;
    if (q >= total) return;

    float4 v = reinterpret_cast<const float4*>(x)[q * (FEATS / 4) + c];
    const int* nb = &g_nbr[q * KNN_K];

#pragma unroll
    for (int n = 0; n < KNN_K; ++n) {
        int j = nb[n];
        float* p = g_sum + (size_t)j * FEATS + c * 4;
        asm volatile("red.global.add.v4.f32 [%0], {%1, %2, %3, %4};"
                     :: "l"(p), "f"(v.x), "f"(v.y), "f"(v.z), "f"(v.w)
                     : "memory");
        if (c == 0)
            asm volatile("red.global.add.u32 [%0], %1;"
                         :: "l"(&g_cnt[j]), "r"(1) : "memory");
    }
}

// ---------------------------------------------------------------------------
// K3: out[r] = sum_d | x[r,d] - sum[r,d] / max(cnt[r],1) |   (warp per node)
// ---------------------------------------------------------------------------
__global__ void out_kernel(const float* __restrict__ x, float* __restrict__ out,
                           int total) {
    int node = (blockIdx.x * blockDim.x + threadIdx.x) >> 5;
    int lane = threadIdx.x & 31;
    if (node >= total) return;

    float c   = (float)g_cnt[node];
    float inv = 1.0f / fmaxf(c, 1.0f);

    const float* xr = x + (size_t)node * FEATS;
    const float* sr = g_sum + (size_t)node * FEATS;

    float acc = fabsf(xr[lane]      - sr[lane]      * inv)
              + fabsf(xr[lane + 32] - sr[lane + 32] * inv);
#pragma unroll
    for (int o = 16; o > 0; o >>= 1) acc += __shfl_xor_sync(0xffffffffu, acc, o);
    if (lane == 0) out[node] = acc;
}

// ---------------------------------------------------------------------------
extern "C" void kernel_launch(void* const* d_in, const int* in_sizes, int n_in,
                              void* d_out, int out_size) {
    const float* x   = (const float*)d_in[0];   // [total, 64] fp32
    const float* pos = (const float*)d_in[1];   // [total, 3]  fp32

    const int total = in_sizes[0] / FEATS;      // 65536
    float* out = (float*)d_out;

    // K0: per-graph counting sort by x (clustering permutation + w precompute)
    sort_kernel<<<BGRAPHS, TPB>>>(pos);

    // K1: kNN over sorted order (smem: 64KB positions + 16KB idx = 80KB)
    size_t smem = (size_t)NODES * sizeof(float4) + NODES * sizeof(int);
    cudaFuncSetAttribute(knn_kernel, cudaFuncAttributeMaxDynamicSharedMemorySize,
                         (int)smem);
    knn_kernel<<<total / QPB, TPB, smem>>>(0);

    // K2: vectorized atomic scatter + counts (16 lanes per query)
    int threads2 = total * 16;
    scatter_kernel<<<(threads2 + 127) / 128, 128>>>(x, total);

    // K3: finalize L1 norm (warp per node)
    out_kernel<<<(total * 32 + 255) / 256, 256>>>(x, out, total);
}

// round 6
// speedup vs baseline: 1.7150x; 1.0641x over previous
#include <cuda_runtime.h>
#include <cuda_bf16.h>
#include <cstdint>

// Problem constants: B=16 graphs, N=4096 nodes/graph, 64 features, k=10.
#define KNN_K      10
#define BGRAPHS    16
#define FEATS      64
#define MAX_TOTAL  65536
#define NODES      4096
#define NPAIR      (NODES / 2)
#define QPB        256
#define NBUCKET    256

// Scratch (device globals: no allocation allowed in kernel_launch)
__device__ float  g_sum[MAX_TOTAL * FEATS];    // 16 MB accumulators
__device__ int    g_cnt[MAX_TOTAL];            // reverse-degree counts
__device__ int    g_nbr[MAX_TOTAL * KNN_K];    // knn neighbor lists (global idx)
__device__ float4 g_spos[MAX_TOTAL];           // x-sorted positions {x,y,z,|p|^2}
__device__ int    g_sidx[MAX_TOTAL];           // sorted-rank -> original local idx

// ---------- packed f32x2 helpers (sm_103a) ----------
__device__ __forceinline__ uint64_t pack2(float a, float b) {
    uint64_t r; asm("mov.b64 %0, {%1, %2};" : "=l"(r) : "f"(a), "f"(b)); return r;
}
__device__ __forceinline__ void unpack2(float& lo, float& hi, uint64_t v) {
    asm("mov.b64 {%0, %1}, %2;" : "=f"(lo), "=f"(hi) : "l"(v));
}
__device__ __forceinline__ uint64_t mul2(uint64_t a, uint64_t b) {
    uint64_t r; asm("mul.rn.f32x2 %0, %1, %2;" : "=l"(r) : "l"(a), "l"(b)); return r;
}
__device__ __forceinline__ uint64_t add2(uint64_t a, uint64_t b) {
    uint64_t r; asm("add.rn.f32x2 %0, %1, %2;" : "=l"(r) : "l"(a), "l"(b)); return r;
}
__device__ __forceinline__ uint64_t fma2(uint64_t a, uint64_t b, uint64_t c) {
    uint64_t r; asm("fma.rn.f32x2 %0, %1, %2, %3;" : "=l"(r) : "l"(a), "l"(b), "l"(c)); return r;
}

// sorted-ascending ripple insert of one u64 key (d2_bits<<32 | orig_idx):
// exact (distance, then original-index) order == jax.lax.top_k tie semantics.
#define INS(cin) do {                                                     \
    uint64_t c_ = (cin);                                                  \
    _Pragma("unroll")                                                     \
    for (int t_ = 0; t_ < KNN_K; ++t_) {                                  \
        uint64_t mn_ = (c_ < kd[t_]) ? c_ : kd[t_];                       \
        uint64_t mx_ = (c_ < kd[t_]) ? kd[t_] : c_;                       \
        kd[t_] = mn_; c_ = mx_;                                           \
    }                                                                     \
    thr = __uint_as_float((unsigned)(kd[KNN_K - 1] >> 32));               \
} while (0)

// distance + conditional insert for one pair; leaves x0_,x1_ defined.
#define PAIR_BODY(jp, x0_, x1_) \
    ulonglong2 xy = pxy[jp];                                              \
    ulonglong2 zw = pzw[jp];                                              \
    uint64_t dot = mul2(qx2, xy.x);                                       \
    dot = fma2(qy2, xy.y, dot);                                           \
    dot = fma2(qz2, zw.x, dot);                                           \
    uint64_t s2  = add2(qsq2, zw.y);                                      \
    uint64_t d2p = fma2(m2, dot, s2);                                     \
    float lo, hi; unpack2(lo, hi, d2p);                                   \
    float x0_, x1_; unpack2(x0_, x1_, xy.x);                              \
    if (fminf(lo, hi) < thr) {                                            \
        int j0_ = (jp) * 2;                                               \
        if (lo < thr && j0_ != qr) {                                      \
            uint64_t key = ((uint64_t)__float_as_uint(lo) << 32)          \
                         | (unsigned)ssid[j0_];                           \
            INS(key);                                                     \
        }                                                                 \
        if (hi < thr && (j0_ + 1) != qr) {                                \
            uint64_t key = ((uint64_t)__float_as_uint(hi) << 32)          \
                         | (unsigned)ssid[j0_ + 1];                       \
            INS(key);                                                     \
        }                                                                 \
    }

// ---------------------------------------------------------------------------
// K0: counting-sort each graph's points by x-bucket (within-bucket order is
// atomic-arbitrary; exactness is preserved because selection uses a total
// order on (d2, orig_idx)). Also precomputes w = |p|^2 (reference rounding).
// ---------------------------------------------------------------------------
__global__ void sort_kernel(const float* __restrict__ pos) {
    __shared__ int cnt[NBUCKET];
    __shared__ int inc[NBUCKET];
    __shared__ int off[NBUCKET];

    const int b   = blockIdx.x;
    const int tid = threadIdx.x;        // 256 threads
    const float* pg = pos + (size_t)b * NODES * 3;

    cnt[tid] = 0;
    __syncthreads();

    for (int j = tid; j < NODES; j += 256) {
        float x = pg[3 * j];
        int bk = (int)floorf((x + 4.0f) * 32.0f);
        bk = max(0, min(NBUCKET - 1, bk));
        atomicAdd(&cnt[bk], 1);
    }
    __syncthreads();

    inc[tid] = cnt[tid];
    __syncthreads();
    for (int d = 1; d < NBUCKET; d <<= 1) {
        int v = (tid >= d) ? inc[tid - d] : 0;
        __syncthreads();
        inc[tid] += v;
        __syncthreads();
    }
    off[tid] = inc[tid] - cnt[tid];
    __syncthreads();

    for (int j = tid; j < NODES; j += 256) {
        float x = pg[3 * j], y = pg[3 * j + 1], z = pg[3 * j + 2];
        float w = x * x + y * y + z * z;
        int bk = (int)floorf((x + 4.0f) * 32.0f);
        bk = max(0, min(NBUCKET - 1, bk));
        int p = atomicAdd(&off[bk], 1);
        g_spos[b * NODES + p] = make_float4(x, y, z, w);
        g_sidx[b * NODES + p] = j;
    }
}

// ---------------------------------------------------------------------------
// K1: x-sorted kNN with EXACT early exit. Queries assigned by sorted rank
// (warp = 32 consecutive ranks). Three phases per warp (all warp-uniform):
//   core: linear scan of ranks [wb-192, wb+224) (clamped) — converges
//         thresholds on nearest candidates, zero vote overhead.
//   up:   expand to higher ranks; break when for ALL lanes the x-gap alone
//         already exceeds thr ((x0-qx)^2 >= thr). x ascending => permanent.
//   down: symmetric toward rank 0.
// Every pair is scanned at most once; exit is provably safe => exact result.
// d2 = (qsq + w) - 2*dot in the reference's rounding order (f32x2 per-lane
// IEEE identical). Self excluded by rank (d2(self)==0 exactly).
// ---------------------------------------------------------------------------
__global__ void __launch_bounds__(QPB) knn_kernel(int dummy) {
    extern __shared__ float4 sm[];
    float4* sxy  = sm;                    // NPAIR {x0,x1,y0,y1}
    float4* szw  = sm + NPAIR;            // NPAIR {z0,z1,w0,w1}
    int*    ssid = (int*)(sm + NODES);    // NODES rank -> orig idx

    const int tilesPerGraph = NODES / QPB;  // 16
    const int b    = blockIdx.x / tilesPerGraph;
    const int tile = blockIdx.x % tilesPerGraph;
    const int tid  = threadIdx.x;
    const int gbase = b * NODES;

    // ---- fused zeroing of accumulators + counts (block-flat region) ----
    {
        float4 z = make_float4(0.f, 0.f, 0.f, 0.f);
        int nb = blockIdx.x * QPB;
        float4* dst = reinterpret_cast<float4*>(g_sum) + (size_t)nb * (FEATS / 4);
#pragma unroll
        for (int i = 0; i < 16; ++i) dst[i * QPB + tid] = z;
        g_cnt[nb + tid] = 0;
    }

    // ---- stage sorted positions (pair-transposed) + rank->orig idx ----
    for (int jp = tid; jp < NPAIR; jp += QPB) {
        float4 a = g_spos[gbase + 2 * jp];
        float4 c = g_spos[gbase + 2 * jp + 1];
        sxy[jp] = make_float4(a.x, c.x, a.y, c.y);
        szw[jp] = make_float4(a.z, c.z, a.w, c.w);
    }
    for (int j = tid; j < NODES; j += QPB)
        ssid[j] = g_sidx[gbase + j];
    __syncthreads();

    // ---- own query = sorted rank qr ----
    const int qr = tile * QPB + tid;
    float qx, qy, qz, qsq;
    {
        float4 xy = sxy[qr >> 1];
        float4 zw = szw[qr >> 1];
        if (qr & 1) { qx = xy.y; qy = xy.w; qz = zw.y; qsq = zw.w; }
        else        { qx = xy.x; qy = xy.z; qz = zw.x; qsq = zw.z; }
    }
    const uint64_t qx2  = pack2(qx, qx);
    const uint64_t qy2  = pack2(qy, qy);
    const uint64_t qz2  = pack2(qz, qz);
    const uint64_t qsq2 = pack2(qsq, qsq);
    const uint64_t m2   = pack2(-2.0f, -2.0f);

    uint64_t kd[KNN_K];
#pragma unroll
    for (int t = 0; t < KNN_K; ++t) kd[t] = 0x7f800000ffffffffULL;
    float thr = __int_as_float(0x7f800000);

    const ulonglong2* pxy = reinterpret_cast<const ulonglong2*>(sxy);
    const ulonglong2* pzw = reinterpret_cast<const ulonglong2*>(szw);

    // warp-uniform core bounds (ranks are multiples of 32 -> pair-aligned)
    const int wb    = tile * QPB + (tid & ~31);        // warp base rank
    const int clo_p = max(0, wb - 192) >> 1;
    const int chi_p = min(NODES, wb + 224) >> 1;

    // ---- core scan (no vote overhead) ----
#pragma unroll 4
    for (int jp = clo_p; jp < chi_p; ++jp) {
        PAIR_BODY(jp, cx0, cx1);
        (void)cx0; (void)cx1;
    }

    // ---- upward expansion with exact early exit ----
    for (int jp = chi_p; jp < NPAIR; ++jp) {
        PAIR_BODY(jp, ux0, ux1);
        (void)ux1;
        float dn = fmaxf(ux0 - qx, 0.0f);   // nearer element of the pair
        if (__all_sync(0xffffffffu, dn * dn >= thr)) break;
    }

    // ---- downward expansion with exact early exit ----
    for (int jp = clo_p - 1; jp >= 0; --jp) {
        PAIR_BODY(jp, dx0, dx1);
        (void)dx0;
        float dn = fmaxf(qx - dx1, 0.0f);   // nearer element of the pair
        if (__all_sync(0xffffffffu, dn * dn >= thr)) break;
    }

    // ---- write neighbor list for this query's ORIGINAL node id ----
    const int my_oid = gbase + ssid[qr];
#pragma unroll
    for (int t = 0; t < KNN_K; ++t)
        g_nbr[my_oid * KNN_K + t] = gbase + (int)(unsigned)kd[t];
}

// ---------------------------------------------------------------------------
// K2: scatter x[query] into g_sum[neighbor] with vectorized L2 reductions,
// plus reverse-degree counting (lane c==0 of each 16-lane query group).
// ---------------------------------------------------------------------------
__global__ void scatter_kernel(const float* __restrict__ x, int total) {
    int t = blockIdx.x * blockDim.x + threadIdx.x;
    int q = t >> 4;
    int c = t & 15;
    if (q >= total) return;

    float4 v = reinterpret_cast<const float4*>(x)[q * (FEATS / 4) + c];
    const int* nb = &g_nbr[q * KNN_K];

#pragma unroll
    for (int n = 0; n < KNN_K; ++n) {
        int j = nb[n];
        float* p = g_sum + (size_t)j * FEATS + c * 4;
        asm volatile("red.global.add.v4.f32 [%0], {%1, %2, %3, %4};"
                     :: "l"(p), "f"(v.x), "f"(v.y), "f"(v.z), "f"(v.w)
                     : "memory");
        if (c == 0)
            asm volatile("red.global.add.u32 [%0], %1;"
                         :: "l"(&g_cnt[j]), "r"(1) : "memory");
    }
}

// ---------------------------------------------------------------------------
// K3: out[r] = sum_d | x[r,d] - sum[r,d] / max(cnt[r],1) |   (warp per node)
// ---------------------------------------------------------------------------
__global__ void out_kernel(const float* __restrict__ x, float* __restrict__ out,
                           int total) {
    int node = (blockIdx.x * blockDim.x + threadIdx.x) >> 5;
    int lane = threadIdx.x & 31;
    if (node >= total) return;

    float c   = (float)g_cnt[node];
    float inv = 1.0f / fmaxf(c, 1.0f);

    const float* xr = x + (size_t)node * FEATS;
    const float* sr = g_sum + (size_t)node * FEATS;

    float acc = fabsf(xr[lane]      - sr[lane]      * inv)
              + fabsf(xr[lane + 32] - sr[lane + 32] * inv);
#pragma unroll
    for (int o = 16; o > 0; o >>= 1) acc += __shfl_xor_sync(0xffffffffu, acc, o);
    if (lane == 0) out[node] = acc;
}

// ---------------------------------------------------------------------------
extern "C" void kernel_launch(void* const* d_in, const int* in_sizes, int n_in,
                              void* d_out, int out_size) {
    const float* x   = (const float*)d_in[0];   // [total, 64] fp32
    const float* pos = (const float*)d_in[1];   // [total, 3]  fp32

    const int total = in_sizes[0] / FEATS;      // 65536
    float* out = (float*)d_out;

    // K0: per-graph counting sort by x
    sort_kernel<<<BGRAPHS, 256>>>(pos);

    // K1: kNN with exact x-gap early exit (smem: 64KB pos + 16KB idx = 80KB)
    size_t smem = (size_t)NODES * sizeof(float4) + NODES * sizeof(int);
    cudaFuncSetAttribute(knn_kernel, cudaFuncAttributeMaxDynamicSharedMemorySize,
                         (int)smem);
    knn_kernel<<<total / QPB, QPB, smem>>>(0);

    // K2: vectorized atomic scatter + counts (16 lanes per query)
    int threads2 = total * 16;
    scatter_kernel<<<(threads2 + 127) / 128, 128>>>(x, total);

    // K3: finalize L1 norm (warp per node)
    out_kernel<<<(total * 32 + 255) / 256, 256>>>(x, out, total);
}

// round 7
// speedup vs baseline: 1.9197x; 1.1194x over previous
#include <cuda_runtime.h>
#include <cuda_bf16.h>
#include <cstdint>

// Problem constants: B=16 graphs, N=4096 nodes/graph, 64 features, k=10.
#define KNN_K      10
#define BGRAPHS    16
#define FEATS      64
#define MAX_TOTAL  65536
#define NODES      4096
#define NPAIR      (NODES / 2)
#define QPB        256
#define NBUCKET    256
#define EXIT_MARGIN 1e-3f     // covers f32 cancellation error in d2 (<=~5e-6)

// Scratch (device globals: no allocation allowed in kernel_launch)
__device__ float  g_sum[MAX_TOTAL * FEATS];    // 16 MB accumulators
__device__ int    g_cnt[MAX_TOTAL];            // reverse-degree counts
__device__ int    g_nbr[MAX_TOTAL * KNN_K];    // knn neighbor lists (global idx)
__device__ float4 g_spos[MAX_TOTAL];           // x-sorted positions {x,y,z,|p|^2}
__device__ int    g_sidx[MAX_TOTAL];           // sorted-rank -> original local idx

// ---------- packed f32x2 helpers (sm_103a) ----------
__device__ __forceinline__ uint64_t pack2(float a, float b) {
    uint64_t r; asm("mov.b64 %0, {%1, %2};" : "=l"(r) : "f"(a), "f"(b)); return r;
}
__device__ __forceinline__ void unpack2(float& lo, float& hi, uint64_t v) {
    asm("mov.b64 {%0, %1}, %2;" : "=f"(lo), "=f"(hi) : "l"(v));
}
__device__ __forceinline__ uint64_t mul2(uint64_t a, uint64_t b) {
    uint64_t r; asm("mul.rn.f32x2 %0, %1, %2;" : "=l"(r) : "l"(a), "l"(b)); return r;
}
__device__ __forceinline__ uint64_t add2(uint64_t a, uint64_t b) {
    uint64_t r; asm("add.rn.f32x2 %0, %1, %2;" : "=l"(r) : "l"(a), "l"(b)); return r;
}
__device__ __forceinline__ uint64_t fma2(uint64_t a, uint64_t b, uint64_t c) {
    uint64_t r; asm("fma.rn.f32x2 %0, %1, %2, %3;" : "=l"(r) : "l"(a), "l"(b), "l"(c)); return r;
}

// sorted-ascending ripple insert of one u64 key (d2_bits<<32 | orig_idx):
// exact (distance, then original-index) order == jax.lax.top_k tie semantics.
#define INS(cin) do {                                                     \
    uint64_t c_ = (cin);                                                  \
    _Pragma("unroll")                                                     \
    for (int t_ = 0; t_ < KNN_K; ++t_) {                                  \
        uint64_t mn_ = (c_ < kd[t_]) ? c_ : kd[t_];                       \
        uint64_t mx_ = (c_ < kd[t_]) ? kd[t_] : c_;                       \
        kd[t_] = mn_; c_ = mx_;                                           \
    }                                                                     \
    thr = __uint_as_float((unsigned)(kd[KNN_K - 1] >> 32));               \
} while (0)

// distance + conditional insert for one pair; leaves x0_,x1_ defined.
#define PAIR_BODY(jp, x0_, x1_) \
    ulonglong2 xy = pxy[jp];                                              \
    ulonglong2 zw = pzw[jp];                                              \
    uint64_t dot = mul2(qx2, xy.x);                                       \
    dot = fma2(qy2, xy.y, dot);                                           \
    dot = fma2(qz2, zw.x, dot);                                           \
    uint64_t s2  = add2(qsq2, zw.y);                                      \
    uint64_t d2p = fma2(m2, dot, s2);                                     \
    float lo, hi; unpack2(lo, hi, d2p);                                   \
    float x0_, x1_; unpack2(x0_, x1_, xy.x);                              \
    if (fminf(lo, hi) < thr) {                                            \
        int j0_ = (jp) * 2;                                               \
        if (lo < thr && j0_ != qr) {                                      \
            uint64_t key = ((uint64_t)__float_as_uint(lo) << 32)          \
                         | (unsigned)ssid[j0_];                           \
            INS(key);                                                     \
        }                                                                 \
        if (hi < thr && (j0_ + 1) != qr) {                                \
            uint64_t key = ((uint64_t)__float_as_uint(hi) << 32)          \
                         | (unsigned)ssid[j0_ + 1];                       \
            INS(key);                                                     \
        }                                                                 \
    }

// ---------------------------------------------------------------------------
// K0: counting-sort each graph's points by x-bucket (within-bucket order is
// atomic-arbitrary; exactness preserved: selection uses a total order on
// (d2, orig_idx)). Precomputes w = |p|^2 with the reference rounding order.
// ---------------------------------------------------------------------------
__global__ void sort_kernel(const float* __restrict__ pos) {
    __shared__ int cnt[NBUCKET];
    __shared__ int inc[NBUCKET];
    __shared__ int off[NBUCKET];

    const int b   = blockIdx.x;
    const int tid = threadIdx.x;        // 256 threads
    const float* pg = pos + (size_t)b * NODES * 3;

    cnt[tid] = 0;
    __syncthreads();

    for (int j = tid; j < NODES; j += 256) {
        float x = pg[3 * j];
        int bk = (int)floorf((x + 4.0f) * 32.0f);
        bk = max(0, min(NBUCKET - 1, bk));
        atomicAdd(&cnt[bk], 1);
    }
    __syncthreads();

    inc[tid] = cnt[tid];
    __syncthreads();
    for (int d = 1; d < NBUCKET; d <<= 1) {
        int v = (tid >= d) ? inc[tid - d] : 0;
        __syncthreads();
        inc[tid] += v;
        __syncthreads();
    }
    off[tid] = inc[tid] - cnt[tid];
    __syncthreads();

    for (int j = tid; j < NODES; j += 256) {
        float x = pg[3 * j], y = pg[3 * j + 1], z = pg[3 * j + 2];
        float w = x * x + y * y + z * z;
        int bk = (int)floorf((x + 4.0f) * 32.0f);
        bk = max(0, min(NBUCKET - 1, bk));
        int p = atomicAdd(&off[bk], 1);
        g_spos[b * NODES + p] = make_float4(x, y, z, w);
        g_sidx[b * NODES + p] = j;
    }
}

// ---------------------------------------------------------------------------
// K1: x-sorted kNN with exact early exit + transverse-radius lane grouping.
// Queries of a 256-rank tile are bitonic-sorted by t = |p|^2 - x^2 so each
// warp's 32 lanes have SIMILAR kNN radii -> the warp-uniform exit fires at
// the lane-mean window instead of the heavy-tailed lane-max.
// Phases (warp-uniform bounds):
//   core: ranks [tile-80, tile+336) clamped — converges thresholds.
//   up/down: expand; break when ALL lanes' x-gap^2 >= thr + EXIT_MARGIN
//            (margin covers computed-d2 cancellation error; x monotone =>
//             condition permanent => exact).
// d2 identical to reference bit-for-bit (2*dot exact => fma == ref rounding).
// ---------------------------------------------------------------------------
__global__ void __launch_bounds__(QPB) knn_kernel(int dummy) {
    extern __shared__ float4 sm[];
    float4* sxy  = sm;                    // NPAIR {x0,x1,y0,y1}
    float4* szw  = sm + NPAIR;            // NPAIR {z0,z1,w0,w1}
    int*    ssid = (int*)(sm + NODES);    // NODES rank -> orig idx
    __shared__ uint64_t skey[QPB];        // (t_bits<<32)|rank for lane grouping

    const int tilesPerGraph = NODES / QPB;  // 16
    const int b    = blockIdx.x / tilesPerGraph;
    const int tile = blockIdx.x % tilesPerGraph;
    const int tid  = threadIdx.x;
    const int gbase = b * NODES;

    // ---- fused zeroing of accumulators + counts (block-flat region) ----
    {
        float4 z = make_float4(0.f, 0.f, 0.f, 0.f);
        int nb = blockIdx.x * QPB;
        float4* dst = reinterpret_cast<float4*>(g_sum) + (size_t)nb * (FEATS / 4);
#pragma unroll
        for (int i = 0; i < 16; ++i) dst[i * QPB + tid] = z;
        g_cnt[nb + tid] = 0;
    }

    // ---- stage sorted positions (pair-transposed) + rank->orig idx ----
    for (int jp = tid; jp < NPAIR; jp += QPB) {
        float4 a = g_spos[gbase + 2 * jp];
        float4 c = g_spos[gbase + 2 * jp + 1];
        sxy[jp] = make_float4(a.x, c.x, a.y, c.y);
        szw[jp] = make_float4(a.z, c.z, a.w, c.w);
    }
    for (int j = tid; j < NODES; j += QPB)
        ssid[j] = g_sidx[gbase + j];
    __syncthreads();

    // ---- lane grouping: bitonic sort tile queries by transverse radius ----
    {
        int   qr0 = tile * QPB + tid;
        float4 xy0 = sxy[qr0 >> 1];
        float4 zw0 = szw[qr0 >> 1];
        float xq = (qr0 & 1) ? xy0.y : xy0.x;
        float wq = (qr0 & 1) ? zw0.w : zw0.z;
        float t  = fmaxf(wq - xq * xq, 0.0f);
        skey[tid] = ((uint64_t)__float_as_uint(t) << 32) | (unsigned)qr0;
    }
    __syncthreads();
    for (int k = 2; k <= QPB; k <<= 1) {
        for (int j = k >> 1; j > 0; j >>= 1) {
            int ixj = tid ^ j;
            if (ixj > tid) {
                uint64_t a = skey[tid], c = skey[ixj];
                bool asc = ((tid & k) == 0);
                if ((a > c) == asc) { skey[tid] = c; skey[ixj] = a; }
            }
            __syncthreads();
        }
    }

    // ---- own query: permuted rank ----
    const int qr = (int)(unsigned)(skey[tid] & 0xffffffffu);
    float qx, qy, qz, qsq;
    {
        float4 xy = sxy[qr >> 1];
        float4 zw = szw[qr >> 1];
        if (qr & 1) { qx = xy.y; qy = xy.w; qz = zw.y; qsq = zw.w; }
        else        { qx = xy.x; qy = xy.z; qz = zw.x; qsq = zw.z; }
    }
    const uint64_t qx2  = pack2(qx, qx);
    const uint64_t qy2  = pack2(qy, qy);
    const uint64_t qz2  = pack2(qz, qz);
    const uint64_t qsq2 = pack2(qsq, qsq);
    const uint64_t m2   = pack2(-2.0f, -2.0f);

    uint64_t kd[KNN_K];
#pragma unroll
    for (int t = 0; t < KNN_K; ++t) kd[t] = 0x7f800000ffffffffULL;
    float thr = __int_as_float(0x7f800000);

    const ulonglong2* pxy = reinterpret_cast<const ulonglong2*>(sxy);
    const ulonglong2* pzw = reinterpret_cast<const ulonglong2*>(szw);

    // warp-uniform core bounds covering the whole tile (+80 margin each side)
    const int tb    = tile * QPB;
    const int clo_p = max(0, tb - 80) >> 1;
    const int chi_p = min(NODES, tb + QPB + 80) >> 1;

    // ---- core scan (no vote overhead) ----
#pragma unroll 4
    for (int jp = clo_p; jp < chi_p; ++jp) {
        PAIR_BODY(jp, cx0, cx1);
        (void)cx0; (void)cx1;
    }

    // ---- upward expansion with exact early exit (margin-protected) ----
    for (int jp = chi_p; jp < NPAIR; ++jp) {
        PAIR_BODY(jp, ux0, ux1);
        (void)ux1;
        float dn = fmaxf(ux0 - qx, 0.0f);   // nearer element of the pair
        if (__all_sync(0xffffffffu, dn * dn >= thr + EXIT_MARGIN)) break;
    }

    // ---- downward expansion with exact early exit ----
    for (int jp = clo_p - 1; jp >= 0; --jp) {
        PAIR_BODY(jp, dx0, dx1);
        (void)dx0;
        float dn = fmaxf(qx - dx1, 0.0f);   // nearer element of the pair
        if (__all_sync(0xffffffffu, dn * dn >= thr + EXIT_MARGIN)) break;
    }

    // ---- write neighbor list for this query's ORIGINAL node id ----
    const int my_oid = gbase + ssid[qr];
#pragma unroll
    for (int t = 0; t < KNN_K; ++t)
        g_nbr[my_oid * KNN_K + t] = gbase + (int)(unsigned)kd[t];
}

// ---------------------------------------------------------------------------
// K2: scatter x[query] into g_sum[neighbor] with vectorized L2 reductions,
// plus reverse-degree counting (lane c==0 of each 16-lane query group).
// ---------------------------------------------------------------------------
__global__ void scatter_kernel(const float* __restrict__ x, int total) {
    int t = blockIdx.x * blockDim.x + threadIdx.x;
    int q = t >> 4;
    int c = t & 15;
    if (q >= total) return;

    float4 v = reinterpret_cast<const float4*>(x)[q * (FEATS / 4) + c];
    const int* nb = &g_nbr[q * KNN_K];

#pragma unroll
    for (int n = 0; n < KNN_K; ++n) {
        int j = nb[n];
        float* p = g_sum + (size_t)j * FEATS + c * 4;
        asm volatile("red.global.add.v4.f32 [%0], {%1, %2, %3, %4};"
                     :: "l"(p), "f"(v.x), "f"(v.y), "f"(v.z), "f"(v.w)
                     : "memory");
        if (c == 0)
            asm volatile("red.global.add.u32 [%0], %1;"
                         :: "l"(&g_cnt[j]), "r"(1) : "memory");
    }
}

// ---------------------------------------------------------------------------
// K3: out[r] = sum_d | x[r,d] - sum[r,d] / max(cnt[r],1) |   (warp per node)
// ---------------------------------------------------------------------------
__global__ void out_kernel(const float* __restrict__ x, float* __restrict__ out,
                           int total) {
    int node = (blockIdx.x * blockDim.x + threadIdx.x) >> 5;
    int lane = threadIdx.x & 31;
    if (node >= total) return;

    float c   = (float)g_cnt[node];
    float inv = 1.0f / fmaxf(c, 1.0f);

    const float* xr = x + (size_t)node * FEATS;
    const float* sr = g_sum + (size_t)node * FEATS;

    float acc = fabsf(xr[lane]      - sr[lane]      * inv)
              + fabsf(xr[lane + 32] - sr[lane + 32] * inv);
#pragma unroll
    for (int o = 16; o > 0; o >>= 1) acc += __shfl_xor_sync(0xffffffffu, acc, o);
    if (lane == 0) out[node] = acc;
}

// ---------------------------------------------------------------------------
extern "C" void kernel_launch(void* const* d_in, const int* in_sizes, int n_in,
                              void* d_out, int out_size) {
    const float* x   = (const float*)d_in[0];   // [total, 64] fp32
    const float* pos = (const float*)d_in[1];   // [total, 3]  fp32

    const int total = in_sizes[0] / FEATS;      // 65536
    float* out = (float*)d_out;

    // K0: per-graph counting sort by x
    sort_kernel<<<BGRAPHS, 256>>>(pos);

    // K1: kNN (smem: 64KB pos + 16KB idx dynamic, +2KB static skey)
    size_t smem = (size_t)NODES * sizeof(float4) + NODES * sizeof(int);
    cudaFuncSetAttribute(knn_kernel, cudaFuncAttributeMaxDynamicSharedMemorySize,
                         (int)smem);
    knn_kernel<<<total / QPB, QPB, smem>>>(0);

    // K2: vectorized atomic scatter + counts (16 lanes per query)
    int threads2 = total * 16;
    scatter_kernel<<<(threads2 + 127) / 128, 128>>>(x, total);

    // K3: finalize L1 norm (warp per node)
    out_kernel<<<(total * 32 + 255) / 256, 256>>>(x, out, total);
}

// round 8
// speedup vs baseline: 2.0453x; 1.0654x over previous
#include <cuda_runtime.h>
#include <cuda_bf16.h>
#include <cstdint>

// Problem constants: B=16 graphs, N=4096 nodes/graph, 64 features, k=10.
#define KNN_K      10
#define BGRAPHS    16
#define FEATS      64
#define MAX_TOTAL  65536
#define NODES      4096
#define NPAIR      (NODES / 2)
#define QPB        256
#define NBUCKET    1024
#define BUCKET_W   (8.0f / NBUCKET)   // x-bucket width (range [-4,4])
#define EXIT_MARGIN 1e-4f             // covers f32 cancellation in computed d2

// Scratch (device globals: no allocation allowed in kernel_launch)
__device__ float  g_sum[MAX_TOTAL * FEATS];    // 16 MB accumulators
__device__ int    g_cnt[MAX_TOTAL];            // reverse-degree counts
__device__ int    g_nbr[MAX_TOTAL * KNN_K];    // knn neighbor lists (global idx)
__device__ float4 g_spos[MAX_TOTAL];           // x-sorted positions {x,y,z,|p|^2}
__device__ int    g_sidx[MAX_TOTAL];           // sorted-rank -> original local idx

// ---------- packed f32x2 helpers (sm_103a) ----------
__device__ __forceinline__ uint64_t pack2(float a, float b) {
    uint64_t r; asm("mov.b64 %0, {%1, %2};" : "=l"(r) : "f"(a), "f"(b)); return r;
}
__device__ __forceinline__ void unpack2(float& lo, float& hi, uint64_t v) {
    asm("mov.b64 {%0, %1}, %2;" : "=f"(lo), "=f"(hi) : "l"(v));
}
__device__ __forceinline__ uint64_t mul2(uint64_t a, uint64_t b) {
    uint64_t r; asm("mul.rn.f32x2 %0, %1, %2;" : "=l"(r) : "l"(a), "l"(b)); return r;
}
__device__ __forceinline__ uint64_t add2(uint64_t a, uint64_t b) {
    uint64_t r; asm("add.rn.f32x2 %0, %1, %2;" : "=l"(r) : "l"(a), "l"(b)); return r;
}
__device__ __forceinline__ uint64_t fma2(uint64_t a, uint64_t b, uint64_t c) {
    uint64_t r; asm("fma.rn.f32x2 %0, %1, %2, %3;" : "=l"(r) : "l"(a), "l"(b), "l"(c)); return r;
}

// sorted-ascending ripple insert of one u64 key (d2_bits<<32 | orig_idx):
// exact (distance, then original-index) order == jax.lax.top_k tie semantics.
#define INS(cin) do {                                                     \
    uint64_t c_ = (cin);                                                  \
    _Pragma("unroll")                                                     \
    for (int t_ = 0; t_ < KNN_K; ++t_) {                                  \
        uint64_t mn_ = (c_ < kd[t_]) ? c_ : kd[t_];                       \
        uint64_t mx_ = (c_ < kd[t_]) ? kd[t_] : c_;                       \
        kd[t_] = mn_; c_ = mx_;                                           \
    }                                                                     \
    thr = __uint_as_float((unsigned)(kd[KNN_K - 1] >> 32));               \
} while (0)

// distance + conditional insert for one pair; exports x0_,x1_.
#define PAIR_BODY(jp, x0_, x1_) \
    ulonglong2 xy = pxy[jp];                                              \
    ulonglong2 zw = pzw[jp];                                              \
    uint64_t dot = mul2(qx2, xy.x);                                       \
    dot = fma2(qy2, xy.y, dot);                                           \
    dot = fma2(qz2, zw.x, dot);                                           \
    uint64_t s2  = add2(qsq2, zw.y);                                      \
    uint64_t d2p = fma2(m2, dot, s2);                                     \
    float lo, hi; unpack2(lo, hi, d2p);                                   \
    float x0_, x1_; unpack2(x0_, x1_, xy.x);                              \
    if (fminf(lo, hi) < thr) {                                            \
        int j0_ = (jp) * 2;                                               \
        if (lo < thr && j0_ != qr) {                                      \
            uint64_t key = ((uint64_t)__float_as_uint(lo) << 32)          \
                         | (unsigned)ssid[j0_];                           \
            INS(key);                                                     \
        }                                                                 \
        if (hi < thr && (j0_ + 1) != qr) {                                \
            uint64_t key = ((uint64_t)__float_as_uint(hi) << 32)          \
                         | (unsigned)ssid[j0_ + 1];                       \
            INS(key);                                                     \
        }                                                                 \
    }

__device__ __forceinline__ int xbucket(float x) {
    int bk = (int)floorf((x + 4.0f) * (NBUCKET / 8.0f));
    return max(0, min(NBUCKET - 1, bk));
}

// ---------------------------------------------------------------------------
// K0: counting-sort each graph's points into 1024 x-buckets (within-bucket
// order is atomic-arbitrary; exactness preserved: selection uses a total
// order on (d2, orig_idx)). w = |p|^2 with exact reference rounding
// (no fma contraction: mul,mul,mul,add,add like jnp.sum(pos*pos)).
// ---------------------------------------------------------------------------
__global__ void sort_kernel(const float* __restrict__ pos) {
    __shared__ int cnt[NBUCKET];
    __shared__ int tsum[256];
    __shared__ int off[NBUCKET];

    const int b   = blockIdx.x;
    const int tid = threadIdx.x;        // 256 threads
    const float* pg = pos + (size_t)b * NODES * 3;

#pragma unroll
    for (int i = 0; i < NBUCKET / 256; ++i) cnt[tid + i * 256] = 0;
    __syncthreads();

    for (int j = tid; j < NODES; j += 256)
        atomicAdd(&cnt[xbucket(pg[3 * j])], 1);
    __syncthreads();

    // two-level exclusive prefix: thread t owns bins [4t, 4t+4)
    {
        int c0 = cnt[4 * tid], c1 = cnt[4 * tid + 1];
        int c2 = cnt[4 * tid + 2], c3 = cnt[4 * tid + 3];
        tsum[tid] = c0 + c1 + c2 + c3;
        __syncthreads();
        // Hillis-Steele inclusive over 256 thread-totals
        for (int d = 1; d < 256; d <<= 1) {
            int v = (tid >= d) ? tsum[tid - d] : 0;
            __syncthreads();
            tsum[tid] += v;
            __syncthreads();
        }
        int base = tsum[tid] - (c0 + c1 + c2 + c3);   // exclusive
        off[4 * tid]     = base;
        off[4 * tid + 1] = base + c0;
        off[4 * tid + 2] = base + c0 + c1;
        off[4 * tid + 3] = base + c0 + c1 + c2;
    }
    __syncthreads();

    for (int j = tid; j < NODES; j += 256) {
        float x = pg[3 * j], y = pg[3 * j + 1], z = pg[3 * j + 2];
        float w = __fadd_rn(__fadd_rn(__fmul_rn(x, x), __fmul_rn(y, y)),
                            __fmul_rn(z, z));        // == jnp.sum(pos*pos)
        int p = atomicAdd(&off[xbucket(x)], 1);
        g_spos[b * NODES + p] = make_float4(x, y, z, w);
        g_sidx[b * NODES + p] = j;
    }
}

// ---------------------------------------------------------------------------
// K1: x-sorted kNN, exact early exit, transverse-radius lane grouping.
// Exit proof (bucket-monotone order): any rank beyond the last processed
// element has x >= x_last - BUCKET_W, so if for all lanes
//   max(x_last - qx - BUCKET_W, 0)^2 >= thr + EXIT_MARGIN
// no future candidate's computed d2 (error <= ~2e-6 << EXIT_MARGIN) can beat
// any lane's current 10th distance -> safe to stop. Symmetric downward.
// Votes amortized over 4-pair chunks. d2 is bit-identical to the reference
// ((qsq+w) - 2*dot: 2*dot exact => single rounding matches).
// ---------------------------------------------------------------------------
__global__ void __launch_bounds__(QPB) knn_kernel(int dummy) {
    extern __shared__ float4 sm[];
    float4* sxy  = sm;                    // NPAIR {x0,x1,y0,y1}
    float4* szw  = sm + NPAIR;            // NPAIR {z0,z1,w0,w1}
    int*    ssid = (int*)(sm + NODES);    // NODES rank -> orig idx
    __shared__ uint64_t skey[QPB];        // (t_bits<<32)|rank for lane grouping

    const int tilesPerGraph = NODES / QPB;  // 16
    const int b    = blockIdx.x / tilesPerGraph;
    const int tile = blockIdx.x % tilesPerGraph;
    const int tid  = threadIdx.x;
    const int gbase = b * NODES;

    // ---- fused zeroing of accumulators + counts (block-flat region) ----
    {
        float4 z = make_float4(0.f, 0.f, 0.f, 0.f);
        int nb = blockIdx.x * QPB;
        float4* dst = reinterpret_cast<float4*>(g_sum) + (size_t)nb * (FEATS / 4);
#pragma unroll
        for (int i = 0; i < 16; ++i) dst[i * QPB + tid] = z;
        g_cnt[nb + tid] = 0;
    }

    // ---- stage sorted positions (pair-transposed) + rank->orig idx ----
    for (int jp = tid; jp < NPAIR; jp += QPB) {
        float4 a = g_spos[gbase + 2 * jp];
        float4 c = g_spos[gbase + 2 * jp + 1];
        sxy[jp] = make_float4(a.x, c.x, a.y, c.y);
        szw[jp] = make_float4(a.z, c.z, a.w, c.w);
    }
    for (int j = tid; j < NODES; j += QPB)
        ssid[j] = g_sidx[gbase + j];
    __syncthreads();

    // ---- lane grouping: bitonic sort tile queries by transverse radius ----
    {
        int   qr0 = tile * QPB + tid;
        float4 xy0 = sxy[qr0 >> 1];
        float4 zw0 = szw[qr0 >> 1];
        float xq = (qr0 & 1) ? xy0.y : xy0.x;
        float wq = (qr0 & 1) ? zw0.w : zw0.z;
        float t  = fmaxf(wq - xq * xq, 0.0f);
        skey[tid] = ((uint64_t)__float_as_uint(t) << 32) | (unsigned)qr0;
    }
    __syncthreads();
    for (int k = 2; k <= QPB; k <<= 1) {
        for (int j = k >> 1; j > 0; j >>= 1) {
            int ixj = tid ^ j;
            if (ixj > tid) {
                uint64_t a = skey[tid], c = skey[ixj];
                bool asc = ((tid & k) == 0);
                if ((a > c) == asc) { skey[tid] = c; skey[ixj] = a; }
            }
            __syncthreads();
        }
    }

    // ---- own query: permuted rank ----
    const int qr = (int)(unsigned)(skey[tid] & 0xffffffffu);
    float qx, qy, qz, qsq;
    {
        float4 xy = sxy[qr >> 1];
        float4 zw = szw[qr >> 1];
        if (qr & 1) { qx = xy.y; qy = xy.w; qz = zw.y; qsq = zw.w; }
        else        { qx = xy.x; qy = xy.z; qz = zw.x; qsq = zw.z; }
    }
    const uint64_t qx2  = pack2(qx, qx);
    const uint64_t qy2  = pack2(qy, qy);
    const uint64_t qz2  = pack2(qz, qz);
    const uint64_t qsq2 = pack2(qsq, qsq);
    const uint64_t m2   = pack2(-2.0f, -2.0f);

    uint64_t kd[KNN_K];
#pragma unroll
    for (int t = 0; t < KNN_K; ++t) kd[t] = 0x7f800000ffffffffULL;
    float thr = __int_as_float(0x7f800000);

    const ulonglong2* pxy = reinterpret_cast<const ulonglong2*>(sxy);
    const ulonglong2* pzw = reinterpret_cast<const ulonglong2*>(szw);

    // warp-uniform core bounds covering the tile (+80 margin each side)
    const int tb    = tile * QPB;
    const int clo_p = max(0, tb - 80) >> 1;
    const int chi_p = min(NODES, tb + QPB + 80) >> 1;

    // ---- core scan (no vote overhead) ----
#pragma unroll 4
    for (int jp = clo_p; jp < chi_p; ++jp) {
        PAIR_BODY(jp, cx0, cx1);
        (void)cx0; (void)cx1;
    }

    // ---- upward expansion: 4-pair chunks, exact bucket-safe exit ----
    for (int jc = chi_p; jc < NPAIR; jc += 4) {
        float lastx = 0.0f;
#pragma unroll
        for (int i = 0; i < 4; ++i) {
            int jp = jc + i;
            if (jp < NPAIR) {
                PAIR_BODY(jp, ux0, ux1);
                (void)ux1;
                lastx = ux0;
            }
        }
        float dn = fmaxf(lastx - qx - BUCKET_W, 0.0f);
        if (__all_sync(0xffffffffu, dn * dn >= thr + EXIT_MARGIN)) break;
    }

    // ---- downward expansion: 4-pair chunks, exact bucket-safe exit ----
    for (int jc = clo_p - 1; jc >= 0; jc -= 4) {
        float lastx = 0.0f;
#pragma unroll
        for (int i = 0; i < 4; ++i) {
            int jp = jc - i;
            if (jp >= 0) {
                PAIR_BODY(jp, dx0, dx1);
                (void)dx0;
                lastx = dx1;
            }
        }
        float dn = fmaxf(qx - lastx - BUCKET_W, 0.0f);
        if (__all_sync(0xffffffffu, dn * dn >= thr + EXIT_MARGIN)) break;
    }

    // ---- write neighbor list for this query's ORIGINAL node id ----
    const int my_oid = gbase + ssid[qr];
#pragma unroll
    for (int t = 0; t < KNN_K; ++t)
        g_nbr[my_oid * KNN_K + t] = gbase + (int)(unsigned)kd[t];
}

// ---------------------------------------------------------------------------
// K2: scatter x[query] into g_sum[neighbor] with vectorized L2 reductions,
// plus reverse-degree counting (lane c==0 of each 16-lane query group).
// ---------------------------------------------------------------------------
__global__ void scatter_kernel(const float* __restrict__ x, int total) {
    int t = blockIdx.x * blockDim.x + threadIdx.x;
    int q = t >> 4;
    int c = t & 15;
    if (q >= total) return;

    float4 v = reinterpret_cast<const float4*>(x)[q * (FEATS / 4) + c];
    const int* nb = &g_nbr[q * KNN_K];

#pragma unroll
    for (int n = 0; n < KNN_K; ++n) {
        int j = nb[n];
        float* p = g_sum + (size_t)j * FEATS + c * 4;
        asm volatile("red.global.add.v4.f32 [%0], {%1, %2, %3, %4};"
                     :: "l"(p), "f"(v.x), "f"(v.y), "f"(v.z), "f"(v.w)
                     : "memory");
        if (c == 0)
            asm volatile("red.global.add.u32 [%0], %1;"
                         :: "l"(&g_cnt[j]), "r"(1) : "memory");
    }
}

// ---------------------------------------------------------------------------
// K3: out[r] = sum_d | x[r,d] - sum[r,d] / max(cnt[r],1) |   (warp per node)
// ---------------------------------------------------------------------------
__global__ void out_kernel(const float* __restrict__ x, float* __restrict__ out,
                           int total) {
    int node = (blockIdx.x * blockDim.x + threadIdx.x) >> 5;
    int lane = threadIdx.x & 31;
    if (node >= total) return;

    float c   = (float)g_cnt[node];
    float inv = 1.0f / fmaxf(c, 1.0f);

    const float* xr = x + (size_t)node * FEATS;
    const float* sr = g_sum + (size_t)node * FEATS;

    float acc = fabsf(xr[lane]      - sr[lane]      * inv)
              + fabsf(xr[lane + 32] - sr[lane + 32] * inv);
#pragma unroll
    for (int o = 16; o > 0; o >>= 1) acc += __shfl_xor_sync(0xffffffffu, acc, o);
    if (lane == 0) out[node] = acc;
}

// ---------------------------------------------------------------------------
extern "C" void kernel_launch(void* const* d_in, const int* in_sizes, int n_in,
                              void* d_out, int out_size) {
    const float* x   = (const float*)d_in[0];   // [total, 64] fp32
    const float* pos = (const float*)d_in[1];   // [total, 3]  fp32

    const int total = in_sizes[0] / FEATS;      // 65536
    float* out = (float*)d_out;

    // K0: per-graph counting sort by x (1024 buckets)
    sort_kernel<<<BGRAPHS, 256>>>(pos);

    // K1: kNN (smem: 64KB pos + 16KB idx dynamic, +2KB static skey)
    size_t smem = (size_t)NODES * sizeof(float4) + NODES * sizeof(int);
    cudaFuncSetAttribute(knn_kernel, cudaFuncAttributeMaxDynamicSharedMemorySize,
                         (int)smem);
    knn_kernel<<<total / QPB, QPB, smem>>>(0);

    // K2: vectorized atomic scatter + counts (16 lanes per query)
    int threads2 = total * 16;
    scatter_kernel<<<(threads2 + 127) / 128, 128>>>(x, total);

    // K3: finalize L1 norm (warp per node)
    out_kernel<<<(total * 32 + 255) / 256, 256>>>(x, out, total);
}